// round 8
// baseline (speedup 1.0000x reference)
#include <cuda_runtime.h>
#include <cuda_fp16.h>
#include <math.h>
#include <limits.h>
#include <stdint.h>

// ---------------- problem constants ----------------
#define Bb   2048
#define Ss   5
#define Nn   80
#define Ee   592
#define FX   8
#define FF   4
#define FE   8
#define Dd   8
#define Hh   800
#define SEQW (Nn*Dd + Ee*Dd)   // 5376
#define G3H  (3*Hh)            // 2400
#define MLP1 1280
#define OUTW (Ss*80)           // 400
#define HPAD 832               // 800 -> x64
#define YPAD 4032              // 4000 -> x64

// ---------------- scratch (device globals, zero-initialized; padding never written) ----
__device__ __align__(128) __half g_seq [(size_t)Bb*Ss*SEQW];
__device__ __align__(128) __half g_wih [(size_t)G3H*SEQW];
__device__ __align__(128) __half g_whh [(size_t)G3H*HPAD];
__device__ __align__(128) __half g_w1t [(size_t)MLP1*YPAD];
__device__ __align__(128) __half g_w2t [(size_t)OUTW*MLP1];
__device__ __align__(128) __half g_hr  [(size_t)Bb*HPAD];
__device__ __align__(128) __half g_y   [(size_t)Bb*YPAD];
__device__ __align__(128) __half g_z   [(size_t)Bb*MLP1];
__device__ __align__(128) float  g_gi  [(size_t)Bb*Ss*G3H];
__device__ __align__(128) float  g_gh  [(size_t)Bb*G3H];
__device__ __align__(128) float  g_h   [(size_t)Bb*Hh];

// ---------------- GNN: one CTA per (b,s) graph; writes half seq ----------------
__global__ __launch_bounds__(256)
void gnn_kernel(const float* __restrict__ x,
                const int*   __restrict__ ei,
                const float* __restrict__ ef,
                const float* __restrict__ ea,
                const float* __restrict__ Wx,
                const float* __restrict__ We,
                const float* __restrict__ Wf,
                const float* __restrict__ Wedge,
                __half* __restrict__ seq)
{
    const int g = blockIdx.x;
    const float* xg  = x  + (size_t)g * Nn * FX;
    const int*   src = ei + (size_t)g * 2 * Ee;
    const int*   dst = src + Ee;
    const float* efg = ef + (size_t)g * Ee * FF;
    const float* eag = ea + (size_t)g * Ee * FE;
    __half* seqg = seq + (size_t)g * SEQW;

    __shared__ float sWx[FX*Dd];
    __shared__ float sWe[FE*Dd];
    __shared__ float sWf[FF*Dd];
    __shared__ float sWedge[(2*Dd+FE)*Dd];
    __shared__ float sagg[Nn*Dd];
    __shared__ float sxo [Nn*Dd];
    __shared__ float sea [Ee*FE];
    __shared__ int   ssrc[Ee], sdst[Ee];
    __shared__ int   sminv;

    const int tid = threadIdx.x;
    if (tid == 0) sminv = INT_MAX;
    if (tid < FX*Dd)  sWx[tid] = Wx[tid];
    if (tid < FE*Dd)  sWe[tid] = We[tid];
    if (tid < FF*Dd)  sWf[tid] = Wf[tid];
    if (tid < 192)    sWedge[tid] = Wedge[tid];
    for (int i = tid; i < Nn*Dd; i += 256) sagg[i] = 0.f;
    for (int i = tid; i < Ee*FE; i += 256) sea[i] = eag[i];
    __syncthreads();

    int lm = INT_MAX;
    for (int e = tid; e < Ee; e += 256) lm = min(lm, src[e]);
    atomicMin(&sminv, lm);
    __syncthreads();
    const int minv = sminv;

    for (int e = tid; e < Ee; e += 256) {
        int s = src[e] - minv;
        int d = dst[e] - minv;
        if (d < 0) d += Nn;
        ssrc[e] = s; sdst[e] = d;
        const float* eae = &sea[e*FE];
        float fe0 = efg[e*FF+0], fe1 = efg[e*FF+1], fe2 = efg[e*FF+2], fe3 = efg[e*FF+3];
        #pragma unroll
        for (int c = 0; c < Dd; c++) {
            float m = 0.f;
            #pragma unroll
            for (int k = 0; k < FE; k++) m += eae[k] * sWe[k*Dd + c];
            m += fe0*sWf[0*Dd+c] + fe1*sWf[1*Dd+c] + fe2*sWf[2*Dd+c] + fe3*sWf[3*Dd+c];
            m = fmaxf(m, 0.f);
            atomicAdd(&sagg[d*Dd + c], m);
        }
    }
    __syncthreads();

    for (int i = tid; i < Nn*Dd; i += 256) {
        int n = i / Dd, c = i % Dd;
        float t = sagg[i];
        #pragma unroll
        for (int k = 0; k < FX; k++) t += xg[n*FX + k] * sWx[k*Dd + c];
        float v = xg[i] + fmaxf(t, 0.f);
        sxo[i] = v;
        seqg[i] = __float2half_rn(v);
    }
    __syncthreads();

    for (int e = tid; e < Ee; e += 256) {
        const float* fs = &sxo[ssrc[e]*Dd];
        const float* fd = &sxo[sdst[e]*Dd];
        const float* eae = &sea[e*FE];
        #pragma unroll
        for (int c = 0; c < Dd; c++) {
            float v = 0.f;
            #pragma unroll
            for (int k = 0; k < Dd; k++) v += fs[k]  * sWedge[(k     )*Dd + c];
            #pragma unroll
            for (int k = 0; k < Dd; k++) v += fd[k]  * sWedge[(Dd + k)*Dd + c];
            #pragma unroll
            for (int k = 0; k < FE; k++) v += eae[k] * sWedge[(2*Dd+k)*Dd + c];
            seqg[Nn*Dd + e*Dd + c] = __float2half_rn(eae[c] + fmaxf(v, 0.f));
        }
    }
}

// ---------------- FP16 tensor-core GEMM (NT), templated on TILE_M -----------------
// C[M,N] = A[M,K] @ B[N,K]^T + bias, mma.m16n8k16.f32.f16, ldmatrix feeds,
// TMR x 128 CTA tile (TMR threads, TMR/32 warps of 64x64), K-tile 64 halfs,
// 3-stage cp.async, one barrier per k-tile. Rows padded to 72 halfs (144B).
// Requires M % TMR == 0, K % 64 == 0; N guarded.

#define SLDH 72
#define NSTG 3

template <int TMR, int OUTM>   // OUTM 0: float out, 1: half out
__global__ __launch_bounds__(TMR, (TMR == 128 ? 2 : 1))
void h16_gemm_nt(const __half* __restrict__ A, const __half* __restrict__ B,
                 const float* __restrict__ bias,
                 float* __restrict__ Cf, __half* __restrict__ Ch,
                 int M, int N, int K)
{
    constexpr uint32_t A_STG = TMR * SLDH * 2;     // bytes per A stage
    constexpr uint32_t B_STG = 128 * SLDH * 2;     // bytes per B stage
    constexpr uint32_t B_OFF = NSTG * A_STG;
    constexpr int ROWSTEP = TMR / 8;
    constexpr int B_ITERS = 1024 / TMR;

    extern __shared__ char smc[];
    const int tid  = threadIdx.x;
    const int bm   = blockIdx.y * TMR;
    const int bn   = blockIdx.x * 128;
    const int warp = tid >> 5;
    const int lane = tid & 31;
    const int gid  = lane >> 2;
    const int tig  = lane & 3;
    const int wm   = (warp >> 1) * 64;
    const int wn   = (warp & 1) * 64;

    float acc[4][8][4];
    #pragma unroll
    for (int i = 0; i < 4; i++)
        #pragma unroll
        for (int j = 0; j < 8; j++)
            #pragma unroll
            for (int v = 0; v < 4; v++) acc[i][j][v] = 0.f;

    const uint32_t s_base = (uint32_t)__cvta_generic_to_shared(smc);
    const int lrow = tid >> 3;
    const int lch  = (tid & 7) * 8;

    const int sel = lane >> 3;
    const int wth = lane & 7;
    const int a_row = (sel & 1) * 8 + wth;
    const int a_k   = (sel >> 1) * 8;
    const int b_row = (sel >> 1) * 8 + wth;
    const int b_k   = (sel & 1) * 8;

    auto load_stage = [&](int stage, int k0) {
        uint32_t a_base = s_base + (uint32_t)stage * A_STG;
        #pragma unroll
        for (int i = 0; i < 8; i++) {
            int row = lrow + i * ROWSTEP;
            uint32_t dst = a_base + (uint32_t)(row * SLDH + lch) * 2u;
            const __half* src = A + (size_t)(bm + row) * K + k0 + lch;
            asm volatile("cp.async.cg.shared.global [%0], [%1], 16;" :: "r"(dst), "l"(src));
        }
        uint32_t b_base = s_base + B_OFF + (uint32_t)stage * B_STG;
        #pragma unroll
        for (int i = 0; i < B_ITERS; i++) {
            int n = lrow + i * ROWSTEP;
            bool valid = (bn + n) < N;
            const __half* src = valid ? (B + (size_t)(bn + n) * K + k0 + lch) : B;
            uint32_t dst = b_base + (uint32_t)(n * SLDH + lch) * 2u;
            int sz = valid ? 16 : 0;
            asm volatile("cp.async.cg.shared.global [%0], [%1], 16, %2;" :: "r"(dst), "l"(src), "r"(sz));
        }
        asm volatile("cp.async.commit_group;");
    };

    auto compute_stage = [&](int stage) {
        const uint32_t abase = s_base + (uint32_t)stage * A_STG
                             + (uint32_t)((wm + a_row) * SLDH + a_k) * 2u;
        const uint32_t bbase = s_base + B_OFF + (uint32_t)stage * B_STG
                             + (uint32_t)((wn + b_row) * SLDH + b_k) * 2u;
        #pragma unroll
        for (int ks = 0; ks < 4; ks++) {
            uint32_t af[4][4], bf[8][2];
            #pragma unroll
            for (int mi = 0; mi < 4; mi++) {
                uint32_t sa = abase + (uint32_t)(mi * 16 * SLDH + ks * 16) * 2u;
                asm volatile(
                    "ldmatrix.sync.aligned.m8n8.x4.shared.b16 {%0,%1,%2,%3}, [%4];"
                    : "=r"(af[mi][0]), "=r"(af[mi][1]), "=r"(af[mi][2]), "=r"(af[mi][3])
                    : "r"(sa));
            }
            #pragma unroll
            for (int nn = 0; nn < 4; nn++) {
                uint32_t sb = bbase + (uint32_t)(nn * 16 * SLDH + ks * 16) * 2u;
                asm volatile(
                    "ldmatrix.sync.aligned.m8n8.x4.shared.b16 {%0,%1,%2,%3}, [%4];"
                    : "=r"(bf[2*nn][0]), "=r"(bf[2*nn][1]),
                      "=r"(bf[2*nn+1][0]), "=r"(bf[2*nn+1][1])
                    : "r"(sb));
            }
            #pragma unroll
            for (int mi = 0; mi < 4; mi++)
                #pragma unroll
                for (int ni = 0; ni < 8; ni++) {
                    asm volatile(
                        "mma.sync.aligned.m16n8k16.row.col.f32.f16.f16.f32 "
                        "{%0,%1,%2,%3}, {%4,%5,%6,%7}, {%8,%9}, {%0,%1,%2,%3};"
                        : "+f"(acc[mi][ni][0]), "+f"(acc[mi][ni][1]),
                          "+f"(acc[mi][ni][2]), "+f"(acc[mi][ni][3])
                        : "r"(af[mi][0]), "r"(af[mi][1]), "r"(af[mi][2]), "r"(af[mi][3]),
                          "r"(bf[ni][0]), "r"(bf[ni][1]));
                }
        }
    };

    const int ntiles = K / 64;
    load_stage(0, 0);
    load_stage(1, 64);

    int stage = 0;
    for (int kt = 0; kt < ntiles; kt++) {
        if (kt == ntiles - 1) { asm volatile("cp.async.wait_group 0;"); }
        else                  { asm volatile("cp.async.wait_group 1;"); }
        __syncthreads();
        if (kt + 2 < ntiles) {
            int ls = stage + 2; if (ls >= NSTG) ls -= NSTG;
            load_stage(ls, (kt + 2) * 64);
        }
        compute_stage(stage);
        if (++stage == NSTG) stage = 0;
    }

    // ---- epilogue ----
    #pragma unroll
    for (int mi = 0; mi < 4; mi++) {
        const int r0 = bm + wm + mi * 16 + gid;
        const int r1 = r0 + 8;
        #pragma unroll
        for (int ni = 0; ni < 8; ni++) {
            const int c0 = bn + wn + ni * 8 + tig * 2;
            if (c0 < N) {
                const float b0 = bias[c0], b1 = bias[c0 + 1];
                float o00 = acc[mi][ni][0] + b0, o01 = acc[mi][ni][1] + b1;
                float o10 = acc[mi][ni][2] + b0, o11 = acc[mi][ni][3] + b1;
                if (OUTM == 0) {
                    *reinterpret_cast<float2*>(Cf + (size_t)r0 * N + c0) = make_float2(o00, o01);
                    *reinterpret_cast<float2*>(Cf + (size_t)r1 * N + c0) = make_float2(o10, o11);
                } else {
                    *reinterpret_cast<__half2*>(Ch + (size_t)r0 * N + c0) = __floats2half2_rn(o00, o01);
                    *reinterpret_cast<__half2*>(Ch + (size_t)r1 * N + c0) = __floats2half2_rn(o10, o11);
                }
            }
        }
    }
}

#define SMEM_128 (NSTG * (128*SLDH*2 + 128*SLDH*2))   // 110592
#define SMEM_256 (NSTG * (256*SLDH*2 + 128*SLDH*2))   // 165888

// ---------------- weight prep ----------------
__global__ __launch_bounds__(256)
void half_copy(const float* __restrict__ in, __half* __restrict__ out, int R, int K, int KP)
{
    int idx = blockIdx.x * blockDim.x + threadIdx.x;
    if (idx >= R * K) return;
    int r = idx / K, k = idx - r * K;
    out[(size_t)r * KP + k] = __float2half_rn(in[idx]);
}

__global__ __launch_bounds__(256)
void half_transpose(const float* __restrict__ in, __half* __restrict__ out, int R, int C, int RP)
{
    __shared__ float t[32][33];
    const int bx = blockIdx.x * 32;
    const int by = blockIdx.y * 32;
    int x = bx + threadIdx.x;
    #pragma unroll
    for (int i = 0; i < 4; i++) {
        int y = by + threadIdx.y + i * 8;
        if (y < R && x < C) t[threadIdx.y + i * 8][threadIdx.x] = in[(size_t)y * C + x];
    }
    __syncthreads();
    x = by + threadIdx.x;
    #pragma unroll
    for (int i = 0; i < 4; i++) {
        int y = bx + threadIdx.y + i * 8;
        if (y < C && x < R)
            out[(size_t)y * RP + x] = __float2half_rn(t[threadIdx.x][threadIdx.y + i * 8]);
    }
}

// ---------------- GRU gates ----------------
__device__ __forceinline__ float sigmoidf(float v) { return 1.f / (1.f + expf(-v)); }

__global__ __launch_bounds__(256)
void gru_gate_kernel(const float* __restrict__ gi, const float* __restrict__ gh,
                     float* __restrict__ h, __half* __restrict__ hr,
                     __half* __restrict__ y, int t)
{
    int idx = blockIdx.x * blockDim.x + threadIdx.x;
    if (idx >= Bb * Hh) return;
    int b = idx / Hh, j = idx - b * Hh;
    const float* gir = gi + (size_t)(b * Ss + t) * G3H;
    const float* ghr = gh + (size_t)b * G3H;
    float ir = gir[j], iz = gir[Hh + j], in = gir[2*Hh + j];
    float hrv = ghr[j], hz = ghr[Hh + j], hn = ghr[2*Hh + j];
    float r = sigmoidf(ir + hrv);
    float z = sigmoidf(iz + hz);
    float n = tanhf(in + r * hn);
    float hold = h[idx];
    float hnew = (1.f - z) * n + z * hold;
    h[idx] = hnew;
    __half hv = __float2half_rn(hnew);
    hr[(size_t)b * HPAD + j] = hv;
    y[(size_t)b * YPAD + t * Hh + j] = hv;
}

__global__ void zero_f32(float* __restrict__ p, int n)
{
    int i = blockIdx.x * blockDim.x + threadIdx.x;
    if (i < n) p[i] = 0.f;
}
__global__ void zero_u32(uint32_t* __restrict__ p, int n)
{
    int i = blockIdx.x * blockDim.x + threadIdx.x;
    if (i < n) p[i] = 0u;
}

// ---------------- launch ----------------
extern "C" void kernel_launch(void* const* d_in, const int* in_sizes, int n_in,
                              void* d_out, int out_size)
{
    const float* x       = (const float*)d_in[0];
    const int*   ei      = (const int*)  d_in[1];
    const float* ef      = (const float*)d_in[2];
    const float* ea      = (const float*)d_in[3];
    const float* Wx      = (const float*)d_in[4];
    const float* We      = (const float*)d_in[5];
    const float* Wf      = (const float*)d_in[6];
    const float* Wedge   = (const float*)d_in[7];
    const float* w_ih    = (const float*)d_in[8];
    const float* w_hh    = (const float*)d_in[9];
    const float* b_ih    = (const float*)d_in[10];
    const float* b_hh    = (const float*)d_in[11];
    const float* mlp_w1  = (const float*)d_in[12];
    const float* mlp_b1  = (const float*)d_in[13];
    const float* mlp_w2  = (const float*)d_in[14];
    const float* mlp_b2  = (const float*)d_in[15];
    float* out = (float*)d_out;

    __half *seq, *wih, *whh, *w1t, *w2t, *hr, *y, *z;
    float *gi, *gh, *h;
    cudaGetSymbolAddress((void**)&seq, g_seq);
    cudaGetSymbolAddress((void**)&wih, g_wih);
    cudaGetSymbolAddress((void**)&whh, g_whh);
    cudaGetSymbolAddress((void**)&w1t, g_w1t);
    cudaGetSymbolAddress((void**)&w2t, g_w2t);
    cudaGetSymbolAddress((void**)&hr,  g_hr);
    cudaGetSymbolAddress((void**)&y,   g_y);
    cudaGetSymbolAddress((void**)&z,   g_z);
    cudaGetSymbolAddress((void**)&gi,  g_gi);
    cudaGetSymbolAddress((void**)&gh,  g_gh);
    cudaGetSymbolAddress((void**)&h,   g_h);

    cudaFuncSetAttribute(h16_gemm_nt<128, 0>,
                         cudaFuncAttributeMaxDynamicSharedMemorySize, SMEM_128);
    cudaFuncSetAttribute(h16_gemm_nt<128, 1>,
                         cudaFuncAttributeMaxDynamicSharedMemorySize, SMEM_128);
    cudaFuncSetAttribute(h16_gemm_nt<256, 0>,
                         cudaFuncAttributeMaxDynamicSharedMemorySize, SMEM_256);

    // 0) weight prep
    {
        int n = G3H * SEQW;
        half_copy<<<(n + 255) / 256, 256>>>(w_ih, wih, G3H, SEQW, SEQW);
        n = G3H * Hh;
        half_copy<<<(n + 255) / 256, 256>>>(w_hh, whh, G3H, Hh, HPAD);
        dim3 blk(32, 8);
        dim3 g1((MLP1 + 31) / 32, (Ss * Hh + 31) / 32);
        half_transpose<<<g1, blk>>>(mlp_w1, w1t, Ss * Hh, MLP1, YPAD);
        dim3 g2((OUTW + 31) / 32, (MLP1 + 31) / 32);
        half_transpose<<<g2, blk>>>(mlp_w2, w2t, MLP1, OUTW, MLP1);
    }

    // 1) GNN -> seq (half)
    gnn_kernel<<<Bb * Ss, 256>>>(x, ei, ef, ea, Wx, We, Wf, Wedge, seq);

    // 2) gi = seq @ w_ih^T + b_ih  [10240, 2400]  — 256-row tiles
    {
        dim3 grid((G3H + 127) / 128, (Bb * Ss) / 256);
        h16_gemm_nt<256, 0><<<grid, 256, SMEM_256>>>(seq, wih, b_ih, gi, nullptr,
                                                     Bb * Ss, G3H, SEQW);
    }

    // 3) GRU recurrence — 128-row tiles (2 CTAs/SM keeps all SMs fed)
    zero_f32<<<(Bb * Hh + 255) / 256, 256>>>(h, Bb * Hh);
    {
        int n = (int)((size_t)Bb * HPAD / 2);
        zero_u32<<<(n + 255) / 256, 256>>>((uint32_t*)hr, n);
    }
    for (int t = 0; t < Ss; t++) {
        dim3 grid((G3H + 127) / 128, Bb / 128);
        h16_gemm_nt<128, 0><<<grid, 128, SMEM_128>>>(hr, whh, b_hh, gh, nullptr,
                                                     Bb, G3H, HPAD);
        gru_gate_kernel<<<(Bb * Hh + 255) / 256, 256>>>(gi, gh, h, hr, y, t);
    }

    // 4) MLP
    {
        dim3 grid((MLP1 + 127) / 128, Bb / 128);
        h16_gemm_nt<128, 1><<<grid, 128, SMEM_128>>>(y, w1t, mlp_b1, nullptr, z,
                                                     Bb, MLP1, YPAD);
    }
    {
        dim3 grid((OUTW + 127) / 128, Bb / 128);
        h16_gemm_nt<128, 0><<<grid, 128, SMEM_128>>>(z, w2t, mlp_b2, out, nullptr,
                                                     Bb, OUTW, MLP1);
    }
}

// round 9
// speedup vs baseline: 1.0205x; 1.0205x over previous
#include <cuda_runtime.h>
#include <cuda_fp16.h>
#include <math.h>
#include <limits.h>
#include <stdint.h>

// ---------------- problem constants ----------------
#define Bb   2048
#define Ss   5
#define Nn   80
#define Ee   592
#define FX   8
#define FF   4
#define FE   8
#define Dd   8
#define Hh   800
#define SEQW (Nn*Dd + Ee*Dd)   // 5376
#define G3H  (3*Hh)            // 2400
#define MLP1 1280
#define OUTW (Ss*80)           // 400
#define HPAD 832               // 800 -> x64
#define YPAD 4032              // 4000 -> x64

// ---------------- scratch (device globals, zero-initialized; padding never written) ----
__device__ __align__(128) __half g_seq [(size_t)Bb*Ss*SEQW];
__device__ __align__(128) __half g_wih [(size_t)G3H*SEQW];
__device__ __align__(128) __half g_whh [(size_t)G3H*HPAD];
__device__ __align__(128) __half g_w1t [(size_t)MLP1*YPAD];
__device__ __align__(128) __half g_w2t [(size_t)OUTW*MLP1];
__device__ __align__(128) __half g_hr  [(size_t)Bb*HPAD];
__device__ __align__(128) __half g_y   [(size_t)Bb*YPAD];
__device__ __align__(128) __half g_z   [(size_t)Bb*MLP1];
__device__ __align__(128) float  g_gi  [(size_t)Bb*Ss*G3H];
__device__ __align__(128) float  g_gh  [(size_t)Bb*G3H];
__device__ __align__(128) float  g_h   [(size_t)Bb*Hh];

// ---------------- GNN: one CTA per (b,s) graph; writes half seq ----------------
__global__ __launch_bounds__(256)
void gnn_kernel(const float* __restrict__ x,
                const int*   __restrict__ ei,
                const float* __restrict__ ef,
                const float* __restrict__ ea,
                const float* __restrict__ Wx,
                const float* __restrict__ We,
                const float* __restrict__ Wf,
                const float* __restrict__ Wedge,
                __half* __restrict__ seq)
{
    const int g = blockIdx.x;
    const float* xg  = x  + (size_t)g * Nn * FX;
    const int*   src = ei + (size_t)g * 2 * Ee;
    const int*   dst = src + Ee;
    const float* efg = ef + (size_t)g * Ee * FF;
    const float* eag = ea + (size_t)g * Ee * FE;
    __half* seqg = seq + (size_t)g * SEQW;

    __shared__ float sWx[FX*Dd];
    __shared__ float sWe[FE*Dd];
    __shared__ float sWf[FF*Dd];
    __shared__ float sWedge[(2*Dd+FE)*Dd];
    __shared__ float sagg[Nn*Dd];
    __shared__ float sxo [Nn*Dd];
    __shared__ float sea [Ee*FE];
    __shared__ int   ssrc[Ee], sdst[Ee];
    __shared__ int   sminv;

    const int tid = threadIdx.x;
    if (tid == 0) sminv = INT_MAX;
    if (tid < FX*Dd)  sWx[tid] = Wx[tid];
    if (tid < FE*Dd)  sWe[tid] = We[tid];
    if (tid < FF*Dd)  sWf[tid] = Wf[tid];
    if (tid < 192)    sWedge[tid] = Wedge[tid];
    for (int i = tid; i < Nn*Dd; i += 256) sagg[i] = 0.f;
    for (int i = tid; i < Ee*FE; i += 256) sea[i] = eag[i];
    __syncthreads();

    int lm = INT_MAX;
    for (int e = tid; e < Ee; e += 256) lm = min(lm, src[e]);
    atomicMin(&sminv, lm);
    __syncthreads();
    const int minv = sminv;

    for (int e = tid; e < Ee; e += 256) {
        int s = src[e] - minv;
        int d = dst[e] - minv;
        if (d < 0) d += Nn;
        ssrc[e] = s; sdst[e] = d;
        const float* eae = &sea[e*FE];
        float fe0 = efg[e*FF+0], fe1 = efg[e*FF+1], fe2 = efg[e*FF+2], fe3 = efg[e*FF+3];
        #pragma unroll
        for (int c = 0; c < Dd; c++) {
            float m = 0.f;
            #pragma unroll
            for (int k = 0; k < FE; k++) m += eae[k] * sWe[k*Dd + c];
            m += fe0*sWf[0*Dd+c] + fe1*sWf[1*Dd+c] + fe2*sWf[2*Dd+c] + fe3*sWf[3*Dd+c];
            m = fmaxf(m, 0.f);
            atomicAdd(&sagg[d*Dd + c], m);
        }
    }
    __syncthreads();

    for (int i = tid; i < Nn*Dd; i += 256) {
        int n = i / Dd, c = i % Dd;
        float t = sagg[i];
        #pragma unroll
        for (int k = 0; k < FX; k++) t += xg[n*FX + k] * sWx[k*Dd + c];
        float v = xg[i] + fmaxf(t, 0.f);
        sxo[i] = v;
        seqg[i] = __float2half_rn(v);
    }
    __syncthreads();

    for (int e = tid; e < Ee; e += 256) {
        const float* fs = &sxo[ssrc[e]*Dd];
        const float* fd = &sxo[sdst[e]*Dd];
        const float* eae = &sea[e*FE];
        #pragma unroll
        for (int c = 0; c < Dd; c++) {
            float v = 0.f;
            #pragma unroll
            for (int k = 0; k < Dd; k++) v += fs[k]  * sWedge[(k     )*Dd + c];
            #pragma unroll
            for (int k = 0; k < Dd; k++) v += fd[k]  * sWedge[(Dd + k)*Dd + c];
            #pragma unroll
            for (int k = 0; k < FE; k++) v += eae[k] * sWedge[(2*Dd+k)*Dd + c];
            seqg[Nn*Dd + e*Dd + c] = __float2half_rn(eae[c] + fmaxf(v, 0.f));
        }
    }
}

// ---------------- FP16 tensor-core GEMM (NT), 128 x TN CTA tile -----------------
// C[M,N] = A[M,K] @ B[N,K]^T + bias, mma.m16n8k16.f32.f16, ldmatrix feeds.
// 128 threads, 4 warps of 64 x (TN/2). K-tile 64 halfs, NST-stage cp.async,
// rows padded to 72 halfs (144B, conflict-free). M%128==0, K%64==0; N guarded.

#define SLDH 72

template <int TN, int NST, int OUTM>   // OUTM 0: float out, 1: half out
__global__ __launch_bounds__(128, 2)
void h16_gemm_nt(const __half* __restrict__ A, const __half* __restrict__ B,
                 const float* __restrict__ bias,
                 float* __restrict__ Cf, __half* __restrict__ Ch,
                 int M, int N, int K)
{
    constexpr uint32_t A_STG = 128 * SLDH * 2;
    constexpr uint32_t B_STG = TN * SLDH * 2;
    constexpr uint32_t B_OFF = NST * A_STG;
    constexpr int B_ITERS = TN / 16;      // B chunk-loads per thread
    constexpr int WN = TN / 2;            // warp n-width
    constexpr int NFR = WN / 8;           // b fragments per warp
    constexpr int NLD = WN / 16;          // x4 ldmatrix per warp for B

    extern __shared__ char smc[];
    const int tid  = threadIdx.x;
    const int bm   = blockIdx.y * 128;
    const int bn   = blockIdx.x * TN;
    const int warp = tid >> 5;
    const int lane = tid & 31;
    const int gid  = lane >> 2;
    const int tig  = lane & 3;
    const int wm   = (warp >> 1) * 64;
    const int wn   = (warp & 1) * WN;

    float acc[4][NFR][4];
    #pragma unroll
    for (int i = 0; i < 4; i++)
        #pragma unroll
        for (int j = 0; j < NFR; j++)
            #pragma unroll
            for (int v = 0; v < 4; v++) acc[i][j][v] = 0.f;

    const uint32_t s_base = (uint32_t)__cvta_generic_to_shared(smc);
    const int lrow = tid >> 3;          // 0..15
    const int lch  = (tid & 7) * 8;

    const int sel = lane >> 3;
    const int wth = lane & 7;
    const int a_row = (sel & 1) * 8 + wth;
    const int a_k   = (sel >> 1) * 8;
    const int b_row = (sel >> 1) * 8 + wth;
    const int b_k   = (sel & 1) * 8;

    auto load_stage = [&](int stage, int k0) {
        uint32_t a_base = s_base + (uint32_t)stage * A_STG;
        #pragma unroll
        for (int i = 0; i < 8; i++) {
            int row = lrow + i * 16;
            uint32_t dst = a_base + (uint32_t)(row * SLDH + lch) * 2u;
            const __half* src = A + (size_t)(bm + row) * K + k0 + lch;
            asm volatile("cp.async.cg.shared.global [%0], [%1], 16;" :: "r"(dst), "l"(src));
        }
        uint32_t b_base = s_base + B_OFF + (uint32_t)stage * B_STG;
        #pragma unroll
        for (int i = 0; i < B_ITERS; i++) {
            int n = lrow + i * 16;
            bool valid = (bn + n) < N;
            const __half* src = valid ? (B + (size_t)(bn + n) * K + k0 + lch) : B;
            uint32_t dst = b_base + (uint32_t)(n * SLDH + lch) * 2u;
            int sz = valid ? 16 : 0;
            asm volatile("cp.async.cg.shared.global [%0], [%1], 16, %2;" :: "r"(dst), "l"(src), "r"(sz));
        }
        asm volatile("cp.async.commit_group;");
    };

    auto compute_stage = [&](int stage) {
        const uint32_t abase = s_base + (uint32_t)stage * A_STG
                             + (uint32_t)((wm + a_row) * SLDH + a_k) * 2u;
        const uint32_t bbase = s_base + B_OFF + (uint32_t)stage * B_STG
                             + (uint32_t)((wn + b_row) * SLDH + b_k) * 2u;
        #pragma unroll
        for (int ks = 0; ks < 4; ks++) {
            uint32_t af[4][4], bf[NFR][2];
            #pragma unroll
            for (int mi = 0; mi < 4; mi++) {
                uint32_t sa = abase + (uint32_t)(mi * 16 * SLDH + ks * 16) * 2u;
                asm volatile(
                    "ldmatrix.sync.aligned.m8n8.x4.shared.b16 {%0,%1,%2,%3}, [%4];"
                    : "=r"(af[mi][0]), "=r"(af[mi][1]), "=r"(af[mi][2]), "=r"(af[mi][3])
                    : "r"(sa));
            }
            #pragma unroll
            for (int nn = 0; nn < NLD; nn++) {
                uint32_t sb = bbase + (uint32_t)(nn * 16 * SLDH + ks * 16) * 2u;
                asm volatile(
                    "ldmatrix.sync.aligned.m8n8.x4.shared.b16 {%0,%1,%2,%3}, [%4];"
                    : "=r"(bf[2*nn][0]), "=r"(bf[2*nn][1]),
                      "=r"(bf[2*nn+1][0]), "=r"(bf[2*nn+1][1])
                    : "r"(sb));
            }
            #pragma unroll
            for (int mi = 0; mi < 4; mi++)
                #pragma unroll
                for (int ni = 0; ni < NFR; ni++) {
                    asm volatile(
                        "mma.sync.aligned.m16n8k16.row.col.f32.f16.f16.f32 "
                        "{%0,%1,%2,%3}, {%4,%5,%6,%7}, {%8,%9}, {%0,%1,%2,%3};"
                        : "+f"(acc[mi][ni][0]), "+f"(acc[mi][ni][1]),
                          "+f"(acc[mi][ni][2]), "+f"(acc[mi][ni][3])
                        : "r"(af[mi][0]), "r"(af[mi][1]), "r"(af[mi][2]), "r"(af[mi][3]),
                          "r"(bf[ni][0]), "r"(bf[ni][1]));
                }
        }
    };

    const int ntiles = K / 64;
    load_stage(0, 0);
    load_stage(1, 64);

    if (NST == 3) {
        int stage = 0;
        for (int kt = 0; kt < ntiles; kt++) {
            if (kt == ntiles - 1) { asm volatile("cp.async.wait_group 0;"); }
            else                  { asm volatile("cp.async.wait_group 1;"); }
            __syncthreads();
            if (kt + 2 < ntiles) {
                int ls = stage + 2; if (ls >= 3) ls -= 3;
                load_stage(ls, (kt + 2) * 64);
            }
            compute_stage(stage);
            if (++stage == 3) stage = 0;
        }
    } else {   // NST == 2: load after compute (buffer reuse hazard otherwise)
        for (int kt = 0; kt < ntiles; kt++) {
            if (kt == ntiles - 1) { asm volatile("cp.async.wait_group 0;"); }
            else                  { asm volatile("cp.async.wait_group 1;"); }
            __syncthreads();
            compute_stage(kt & 1);
            if (kt + 2 < ntiles) {
                __syncthreads();
                load_stage(kt & 1, (kt + 2) * 64);
            }
        }
    }

    // ---- epilogue ----
    #pragma unroll
    for (int mi = 0; mi < 4; mi++) {
        const int r0 = bm + wm + mi * 16 + gid;
        const int r1 = r0 + 8;
        #pragma unroll
        for (int ni = 0; ni < NFR; ni++) {
            const int c0 = bn + wn + ni * 8 + tig * 2;
            if (c0 < N) {
                const float b0 = bias[c0], b1 = bias[c0 + 1];
                float o00 = acc[mi][ni][0] + b0, o01 = acc[mi][ni][1] + b1;
                float o10 = acc[mi][ni][2] + b0, o11 = acc[mi][ni][3] + b1;
                if (OUTM == 0) {
                    *reinterpret_cast<float2*>(Cf + (size_t)r0 * N + c0) = make_float2(o00, o01);
                    *reinterpret_cast<float2*>(Cf + (size_t)r1 * N + c0) = make_float2(o10, o11);
                } else {
                    *reinterpret_cast<__half2*>(Ch + (size_t)r0 * N + c0) = __floats2half2_rn(o00, o01);
                    *reinterpret_cast<__half2*>(Ch + (size_t)r1 * N + c0) = __floats2half2_rn(o10, o11);
                }
            }
        }
    }
}

#define SMEM_N128 (3 * (128*SLDH*2 + 128*SLDH*2))   // 110592
#define SMEM_N160 (2 * (128*SLDH*2 + 160*SLDH*2))   //  82944

// ---------------- weight prep ----------------
__global__ __launch_bounds__(256)
void half_copy(const float* __restrict__ in, __half* __restrict__ out, int R, int K, int KP)
{
    int idx = blockIdx.x * blockDim.x + threadIdx.x;
    if (idx >= R * K) return;
    int r = idx / K, k = idx - r * K;
    out[(size_t)r * KP + k] = __float2half_rn(in[idx]);
}

__global__ __launch_bounds__(256)
void half_transpose(const float* __restrict__ in, __half* __restrict__ out, int R, int C, int RP)
{
    __shared__ float t[32][33];
    const int bx = blockIdx.x * 32;
    const int by = blockIdx.y * 32;
    int x = bx + threadIdx.x;
    #pragma unroll
    for (int i = 0; i < 4; i++) {
        int y = by + threadIdx.y + i * 8;
        if (y < R && x < C) t[threadIdx.y + i * 8][threadIdx.x] = in[(size_t)y * C + x];
    }
    __syncthreads();
    x = by + threadIdx.x;
    #pragma unroll
    for (int i = 0; i < 4; i++) {
        int y = bx + threadIdx.y + i * 8;
        if (y < C && x < R)
            out[(size_t)y * RP + x] = __float2half_rn(t[threadIdx.x][threadIdx.y + i * 8]);
    }
}

// ---------------- GRU gates ----------------
__device__ __forceinline__ float sigmoidf(float v) { return 1.f / (1.f + expf(-v)); }

// T0 == 1: first timestep, h == 0, gh == b_hh (no GEMM, no h read)
template <int T0>
__global__ __launch_bounds__(256)
void gru_gate_kernel(const float* __restrict__ gi, const float* __restrict__ gh,
                     float* __restrict__ h, __half* __restrict__ hr,
                     __half* __restrict__ y, int t)
{
    int idx = blockIdx.x * blockDim.x + threadIdx.x;
    if (idx >= Bb * Hh) return;
    int b = idx / Hh, j = idx - b * Hh;
    const float* gir = gi + (size_t)(b * Ss + t) * G3H;
    const float* ghr = T0 ? gh : (gh + (size_t)b * G3H);   // T0: gh = b_hh [G3H]
    float ir = gir[j], iz = gir[Hh + j], in = gir[2*Hh + j];
    float hrv = ghr[j], hz = ghr[Hh + j], hn = ghr[2*Hh + j];
    float r = sigmoidf(ir + hrv);
    float z = sigmoidf(iz + hz);
    float n = tanhf(in + r * hn);
    float hnew;
    if (T0) hnew = (1.f - z) * n;
    else    hnew = (1.f - z) * n + z * h[idx];
    h[idx] = hnew;
    __half hv = __float2half_rn(hnew);
    hr[(size_t)b * HPAD + j] = hv;
    y[(size_t)b * YPAD + t * Hh + j] = hv;
}

// ---------------- launch ----------------
extern "C" void kernel_launch(void* const* d_in, const int* in_sizes, int n_in,
                              void* d_out, int out_size)
{
    const float* x       = (const float*)d_in[0];
    const int*   ei      = (const int*)  d_in[1];
    const float* ef      = (const float*)d_in[2];
    const float* ea      = (const float*)d_in[3];
    const float* Wx      = (const float*)d_in[4];
    const float* We      = (const float*)d_in[5];
    const float* Wf      = (const float*)d_in[6];
    const float* Wedge   = (const float*)d_in[7];
    const float* w_ih    = (const float*)d_in[8];
    const float* w_hh    = (const float*)d_in[9];
    const float* b_ih    = (const float*)d_in[10];
    const float* b_hh    = (const float*)d_in[11];
    const float* mlp_w1  = (const float*)d_in[12];
    const float* mlp_b1  = (const float*)d_in[13];
    const float* mlp_w2  = (const float*)d_in[14];
    const float* mlp_b2  = (const float*)d_in[15];
    float* out = (float*)d_out;

    __half *seq, *wih, *whh, *w1t, *w2t, *hr, *y, *z;
    float *gi, *gh, *h;
    cudaGetSymbolAddress((void**)&seq, g_seq);
    cudaGetSymbolAddress((void**)&wih, g_wih);
    cudaGetSymbolAddress((void**)&whh, g_whh);
    cudaGetSymbolAddress((void**)&w1t, g_w1t);
    cudaGetSymbolAddress((void**)&w2t, g_w2t);
    cudaGetSymbolAddress((void**)&hr,  g_hr);
    cudaGetSymbolAddress((void**)&y,   g_y);
    cudaGetSymbolAddress((void**)&z,   g_z);
    cudaGetSymbolAddress((void**)&gi,  g_gi);
    cudaGetSymbolAddress((void**)&gh,  g_gh);
    cudaGetSymbolAddress((void**)&h,   g_h);

    cudaFuncSetAttribute(h16_gemm_nt<128, 3, 0>,
                         cudaFuncAttributeMaxDynamicSharedMemorySize, SMEM_N128);
    cudaFuncSetAttribute(h16_gemm_nt<128, 3, 1>,
                         cudaFuncAttributeMaxDynamicSharedMemorySize, SMEM_N128);
    cudaFuncSetAttribute(h16_gemm_nt<160, 2, 0>,
                         cudaFuncAttributeMaxDynamicSharedMemorySize, SMEM_N160);

    // 0) weight prep
    {
        int n = G3H * SEQW;
        half_copy<<<(n + 255) / 256, 256>>>(w_ih, wih, G3H, SEQW, SEQW);
        n = G3H * Hh;
        half_copy<<<(n + 255) / 256, 256>>>(w_hh, whh, G3H, Hh, HPAD);
        dim3 blk(32, 8);
        dim3 g1((MLP1 + 31) / 32, (Ss * Hh + 31) / 32);
        half_transpose<<<g1, blk>>>(mlp_w1, w1t, Ss * Hh, MLP1, YPAD);
        dim3 g2((OUTW + 31) / 32, (MLP1 + 31) / 32);
        half_transpose<<<g2, blk>>>(mlp_w2, w2t, MLP1, OUTW, MLP1);
    }

    // 1) GNN -> seq (half)
    gnn_kernel<<<Bb * Ss, 256>>>(x, ei, ef, ea, Wx, We, Wf, Wedge, seq);

    // 2) gi = seq @ w_ih^T + b_ih  [10240, 2400]
    {
        dim3 grid(19, (Bb * Ss) / 128);
        h16_gemm_nt<128, 3, 0><<<grid, 128, SMEM_N128>>>(seq, wih, b_ih, gi, nullptr,
                                                         Bb * Ss, G3H, SEQW);
    }

    // 3) GRU recurrence.  t=0: h==0 => gh == b_hh, no GEMM needed.
    gru_gate_kernel<1><<<(Bb * Hh + 255) / 256, 256>>>(gi, b_hh, h, hr, y, 0);
    for (int t = 1; t < Ss; t++) {
        dim3 grid(15, Bb / 128);        // 240 CTAs -> single wave at 2 CTA/SM
        h16_gemm_nt<160, 2, 0><<<grid, 128, SMEM_N160>>>(hr, whh, b_hh, gh, nullptr,
                                                         Bb, G3H, HPAD);
        gru_gate_kernel<0><<<(Bb * Hh + 255) / 256, 256>>>(gi, gh, h, hr, y, t);
    }

    // 4) MLP
    {
        dim3 grid(10, Bb / 128);
        h16_gemm_nt<128, 3, 1><<<grid, 128, SMEM_N128>>>(y, w1t, mlp_b1, nullptr, z,
                                                         Bb, MLP1, YPAD);
    }
    {
        dim3 grid(4, Bb / 128);
        h16_gemm_nt<128, 3, 0><<<grid, 128, SMEM_N128>>>(z, w2t, mlp_b2, out, nullptr,
                                                         Bb, OUTW, MLP1);
    }
}